// round 4
// baseline (speedup 1.0000x reference)
#include <cuda_runtime.h>

#define B 8
#define N 2048
#define D 64
#define ALPHA 0.2f

// Scratch (no allocations allowed): h [B,N,D], s/t [B,N], S_all [B,D]
__device__ float g_h[B * N * D];
__device__ float g_s[B * N];
__device__ float g_t[B * N];
__device__ float g_S[B * D];

__global__ void k_init() {
    int i = threadIdx.x;
    if (i < B * D) g_S[i] = 0.f;
}

// h = x @ W  (per block: 32 rows), plus partial column-sums S_all via atomics.
__global__ __launch_bounds__(256) void k_h(const float* __restrict__ x,
                                           const float* __restrict__ W) {
    __shared__ float Ws[64 * 64];
    __shared__ float xs[4][64];
    __shared__ float red[4][64];
    int tx = threadIdx.x, ty = threadIdx.y;
    int tid = ty * 64 + tx;
    for (int k = tid; k < 64 * 64; k += 256) Ws[k] = W[k];

    int rowBase = blockIdx.x * 32;       // flattened row over B*N (32 | N)
    int b = rowBase / N;
    float part = 0.f;
    for (int rt = 0; rt < 8; rt++) {
        int r = rowBase + rt * 4;
        __syncthreads();
        xs[ty][tx] = x[(r + ty) * 64 + tx];
        __syncthreads();
        float acc = 0.f;
#pragma unroll
        for (int i = 0; i < 64; i++)
            acc = fmaf(xs[ty][i], Ws[i * 64 + tx], acc);
        g_h[(r + ty) * 64 + tx] = acc;
        part += acc;
    }
    red[ty][tx] = part;
    __syncthreads();
    if (ty == 0) {
        float ssum = red[0][tx] + red[1][tx] + red[2][tx] + red[3][tx];
        atomicAdd(&g_S[b * 64 + tx], ssum);
    }
}

// s[r] = h[r]·a[0:64], t[r] = h[r]·a[64:128]; one warp per row.
__global__ __launch_bounds__(256) void k_st(const float* __restrict__ a) {
    int w = blockIdx.x * 8 + (threadIdx.x >> 5);
    int lane = threadIdx.x & 31;
    const float* hr = g_h + w * 64;
    float h0 = hr[lane], h1 = hr[lane + 32];
    float sp = fmaf(h0, a[lane], h1 * a[lane + 32]);
    float tp = fmaf(h0, a[64 + lane], h1 * a[96 + lane]);
#pragma unroll
    for (int o = 16; o > 0; o >>= 1) {
        sp += __shfl_xor_sync(0xffffffffu, sp, o);
        tp += __shfl_xor_sync(0xffffffffu, tp, o);
    }
    if (lane == 0) { g_s[w] = sp; g_t[w] = tp; }
}

// One block per row i. Phase 1: compact neighbor list (adj row + forced diag).
// Phase 2: warp b = batch b; lanes cover 64 dims as float2.
// out[b,i,:] = (S_all + sum_nbr (exp(lrelu(s_i+t_j))-1) * h[b,j,:]) / (N + sum c) + bias
__global__ __launch_bounds__(256) void k_main(const float* __restrict__ adj,
                                              const float* __restrict__ bias,
                                              float* __restrict__ out) {
    __shared__ unsigned short nbr[N];
    __shared__ int cnt;
    int i = blockIdx.x;
    int tid = threadIdx.x;
    if (tid == 0) cnt = 0;
    __syncthreads();
    const float* arow = adj + (size_t)i * N;
    for (int j = tid; j < N; j += 256) {
        if (arow[j] != 0.f || j == i) {
            int p = atomicAdd(&cnt, 1);
            nbr[p] = (unsigned short)j;
        }
    }
    __syncthreads();
    int c_n = cnt;

    int b = tid >> 5, lane = tid & 31;
    float s = g_s[b * N + i];
    const float* tb = g_t + b * N;
    const float2* h2 = (const float2*)(g_h + b * N * D);
    float acc0 = 0.f, acc1 = 0.f, z = 0.f;
#pragma unroll 4
    for (int k = 0; k < c_n; k++) {
        int j = nbr[k];
        float tv = tb[j];                 // uniform across warp -> 1 sector
        float v = s + tv;
        float lr = v > 0.f ? v : ALPHA * v;
        float c = __expf(lr) - 1.f;
        float2 hv = h2[j * 32 + lane];    // coalesced 256B/warp
        acc0 = fmaf(c, hv.x, acc0);
        acc1 = fmaf(c, hv.y, acc1);
        z += c;
    }
    float inv = 1.f / ((float)N + z);
    int d0 = lane * 2;
    int o = (b * N + i) * D + d0;
    out[o]     = (g_S[b * D + d0]     + acc0) * inv + bias[d0];
    out[o + 1] = (g_S[b * D + d0 + 1] + acc1) * inv + bias[d0 + 1];
}

extern "C" void kernel_launch(void* const* d_in, const int* in_sizes, int n_in,
                              void* d_out, int out_size) {
    const float* x    = (const float*)d_in[0];  // [B,N,64]
    const float* adj  = (const float*)d_in[1];  // [N,N]
    const float* W    = (const float*)d_in[2];  // [64,64]
    const float* a    = (const float*)d_in[3];  // [128,1]
    const float* bias = (const float*)d_in[4];  // [64]
    float* out = (float*)d_out;                 // [B,N,64]

    k_init<<<1, 512>>>();
    k_h<<<(B * N) / 32, dim3(64, 4)>>>(x, W);
    k_st<<<(B * N) / 8, 256>>>(a);
    k_main<<<N, 256>>>(adj, bias, out);
}

// round 5
// speedup vs baseline: 1.2323x; 1.2323x over previous
#include <cuda_runtime.h>

#define B 8
#define N 2048
#define D 64
#define ALPHA 0.2f
#define TILE 256

// Scratch: h [B,N,D]; per-row packs (s,e^s,e^{as}) and (t,e^t,e^{at}); colsums S
__device__ float  g_h[B * N * D];
__device__ float4 g_se[B * N];
__device__ float4 g_te[B * N];
__device__ float  g_S[B * D];

__global__ void k_init() {
    int i = threadIdx.x;
    if (i < B * D) g_S[i] = 0.f;
}

// Fused: h = x@W, column-sums S (atomics), and s/t row-dots + exp packs.
// Block: (64,4), 32 rows per block.
__global__ __launch_bounds__(256) void k_h(const float* __restrict__ x,
                                           const float* __restrict__ W,
                                           const float* __restrict__ a) {
    __shared__ float Ws[64 * 64];
    __shared__ float xs[4][64];
    __shared__ float red[4][64];
    __shared__ float redS[8][4][2];
    __shared__ float redT[8][4][2];
    int tx = threadIdx.x, ty = threadIdx.y;
    int tid = ty * 64 + tx;
    for (int k = tid; k < 64 * 64; k += 256) Ws[k] = W[k];

    float a0 = a[tx];        // a[:64]
    float a1 = a[64 + tx];   // a[64:]
    int rowBase = blockIdx.x * 32;   // flattened over B*N (32 | N)
    int b = rowBase / N;
    float part = 0.f;
    float accs[8];
#pragma unroll
    for (int rt = 0; rt < 8; rt++) {
        int r = rowBase + rt * 4;
        __syncthreads();
        xs[ty][tx] = x[(r + ty) * 64 + tx];
        __syncthreads();
        float acc = 0.f;
#pragma unroll
        for (int i = 0; i < 64; i++)
            acc = fmaf(xs[ty][i], Ws[i * 64 + tx], acc);
        g_h[(r + ty) * 64 + tx] = acc;
        part += acc;
        accs[rt] = acc;
    }
    // s/t reductions: each warp holds one ty, one 32-col half
    int lane = tid & 31, half = tx >> 5;
#pragma unroll
    for (int rt = 0; rt < 8; rt++) {
        float sp = accs[rt] * a0;
        float tp = accs[rt] * a1;
#pragma unroll
        for (int o = 16; o > 0; o >>= 1) {
            sp += __shfl_xor_sync(0xffffffffu, sp, o);
            tp += __shfl_xor_sync(0xffffffffu, tp, o);
        }
        if (lane == 0) { redS[rt][ty][half] = sp; redT[rt][ty][half] = tp; }
    }
    red[ty][tx] = part;
    __syncthreads();
    if (tid < 32) {
        int rt = tid >> 2, tyy = tid & 3;
        float s = redS[rt][tyy][0] + redS[rt][tyy][1];
        float t = redT[rt][tyy][0] + redT[rt][tyy][1];
        int r = rowBase + rt * 4 + tyy;
        g_se[r] = make_float4(s, __expf(s), __expf(ALPHA * s), 0.f);
        g_te[r] = make_float4(t, __expf(t), __expf(ALPHA * t), 0.f);
    }
    if (ty == 0) {
        float ssum = red[0][tx] + red[1][tx] + red[2][tx] + red[3][tx];
        atomicAdd(&g_S[b * 64 + tx], ssum);
    }
}

// One block per row i. Phase 1: compact neighbor list (adj row + forced diag).
// Phase 2 (tiled): cooperatively compute c[b][k] via factored exps into smem,
// then warp b accumulates: out[b,i,:] = (S + sum c_j h[b,j,:])/(N + sum c) + bias
__global__ __launch_bounds__(256) void k_main(const float* __restrict__ adj,
                                              const float* __restrict__ bias,
                                              float* __restrict__ out) {
    __shared__ unsigned short nbr[N];
    __shared__ float cs[8][TILE];
    __shared__ float sh_negs[8], sh_f1[8], sh_fa[8];
    __shared__ int cnt;
    int i = blockIdx.x, tid = threadIdx.x;
    if (tid == 0) cnt = 0;
    if (tid < 8) {
        float4 se = g_se[tid * N + i];
        sh_negs[tid] = -se.x; sh_f1[tid] = se.y; sh_fa[tid] = se.z;
    }
    __syncthreads();
    const float* arow = adj + (size_t)i * N;
    for (int j = tid; j < N; j += 256) {
        if (arow[j] != 0.f || j == i) {
            int p = atomicAdd(&cnt, 1);
            nbr[p] = (unsigned short)j;
        }
    }
    __syncthreads();
    int c_n = cnt;

    int b = tid >> 5, lane = tid & 31;
    const float2* h2 = (const float2*)(g_h + b * N * D);
    float acc0 = 0.f, acc1 = 0.f, z = 0.f;

    for (int t0 = 0; t0 < c_n; t0 += TILE) {
        int tl = min(TILE, c_n - t0);
        // compute coefficients: idx -> (bb = idx>>8, kk = idx&255)
        for (int idx = tid; idx < 8 * TILE; idx += 256) {
            int bb = idx >> 8;
            int kk = idx & (TILE - 1);
            if (kk < tl) {
                int j = nbr[t0 + kk];
                float4 te = g_te[bb * N + j];
                float c = (te.x > sh_negs[bb]) ? fmaf(sh_f1[bb], te.y, -1.f)
                                               : fmaf(sh_fa[bb], te.z, -1.f);
                cs[bb][kk] = c;
            }
        }
        __syncthreads();
#pragma unroll 4
        for (int kk = 0; kk < tl; kk++) {
            int j = nbr[t0 + kk];
            float c = cs[b][kk];
            float2 hv = h2[j * 32 + lane];   // coalesced 256B/warp, L2-resident
            acc0 = fmaf(c, hv.x, acc0);
            acc1 = fmaf(c, hv.y, acc1);
            z += c;
        }
        __syncthreads();
    }
    float inv = 1.f / ((float)N + z);
    int d0 = lane * 2;
    int o = (b * N + i) * D + d0;
    out[o]     = (g_S[b * D + d0]     + acc0) * inv + bias[d0];
    out[o + 1] = (g_S[b * D + d0 + 1] + acc1) * inv + bias[d0 + 1];
}

extern "C" void kernel_launch(void* const* d_in, const int* in_sizes, int n_in,
                              void* d_out, int out_size) {
    const float* x    = (const float*)d_in[0];  // [B,N,64]
    const float* adj  = (const float*)d_in[1];  // [N,N]
    const float* W    = (const float*)d_in[2];  // [64,64]
    const float* a    = (const float*)d_in[3];  // [128,1]
    const float* bias = (const float*)d_in[4];  // [64]
    float* out = (float*)d_out;                 // [B,N,64]

    k_init<<<1, 512>>>();
    k_h<<<(B * N) / 32, dim3(64, 4)>>>(x, W, a);
    k_main<<<N, 256>>>(adj, bias, out);
}

// round 6
// speedup vs baseline: 2.0965x; 1.7013x over previous
#include <cuda_runtime.h>

#define B 8
#define N 2048
#define D 64
#define ALPHA 0.2f
#define TILE 256

// Scratch: h [B,N,D]; per-row packs (s,e^s,e^{as},0)/(t,e^t,e^{at},0); colsums S
__device__ __align__(16) float  g_h[B * N * D];
__device__ __align__(16) float4 g_se[B * N];
__device__ __align__(16) float4 g_te[B * N];
__device__ __align__(16) float  g_S[B * D];

__global__ void k_init() {
    int i = threadIdx.x;
    if (i < B * D) g_S[i] = 0.f;
}

// Fused: h = x@W, column-sums S (atomics), s/t row-dots + exp packs.
// Block (64,4); 32 rows per block; grid = B*N/32 = 512.
__global__ __launch_bounds__(256) void k_h(const float* __restrict__ x,
                                           const float* __restrict__ W,
                                           const float* __restrict__ a) {
    __shared__ float Ws[64 * 64];
    __shared__ float xs[32][64];
    __shared__ float red[4][64];
    __shared__ float redS[8][4][2];
    __shared__ float redT[8][4][2];
    int tx = threadIdx.x, ty = threadIdx.y;
    int tid = ty * 64 + tx;

    // Load W (4096 floats) and the 32 x-rows (2048 floats) via float4
    const float4* W4 = (const float4*)W;
    float4* Ws4 = (float4*)Ws;
    for (int k = tid; k < 1024; k += 256) Ws4[k] = W4[k];
    int rowBase = blockIdx.x * 32;                // flattened over B*N (32 | N)
    int b = rowBase / N;
    const float4* x4 = ((const float4*)x) + rowBase * 16;
    float4* xs4 = (float4*)&xs[0][0];
    for (int k = tid; k < 512; k += 256) xs4[k] = x4[k];
    __syncthreads();

    float a0 = a[tx];        // a[:64]
    float a1 = a[64 + tx];   // a[64:]
    float part = 0.f;
    float accs[8];
#pragma unroll
    for (int rt = 0; rt < 8; rt++) {
        int r = rt * 4 + ty;                      // local row
        const float4* xr = (const float4*)xs[r];
        float acc = 0.f;
#pragma unroll
        for (int i4 = 0; i4 < 16; i4++) {
            float4 xv = xr[i4];
            acc = fmaf(xv.x, Ws[(i4 * 4 + 0) * 64 + tx], acc);
            acc = fmaf(xv.y, Ws[(i4 * 4 + 1) * 64 + tx], acc);
            acc = fmaf(xv.z, Ws[(i4 * 4 + 2) * 64 + tx], acc);
            acc = fmaf(xv.w, Ws[(i4 * 4 + 3) * 64 + tx], acc);
        }
        g_h[(rowBase + r) * 64 + tx] = acc;
        part += acc;
        accs[rt] = acc;
    }
    // s/t reductions: warp = (ty, 32-col half)
    int lane = tid & 31, half = tx >> 5;
#pragma unroll
    for (int rt = 0; rt < 8; rt++) {
        float sp = accs[rt] * a0;
        float tp = accs[rt] * a1;
#pragma unroll
        for (int o = 16; o > 0; o >>= 1) {
            sp += __shfl_xor_sync(0xffffffffu, sp, o);
            tp += __shfl_xor_sync(0xffffffffu, tp, o);
        }
        if (lane == 0) { redS[rt][ty][half] = sp; redT[rt][ty][half] = tp; }
    }
    red[ty][tx] = part;
    __syncthreads();
    if (tid < 32) {
        int rt = tid >> 2, tyy = tid & 3;
        float s = redS[rt][tyy][0] + redS[rt][tyy][1];
        float t = redT[rt][tyy][0] + redT[rt][tyy][1];
        int r = rowBase + rt * 4 + tyy;
        g_se[r] = make_float4(s, __expf(s), __expf(ALPHA * s), 0.f);
        g_te[r] = make_float4(t, __expf(t), __expf(ALPHA * t), 0.f);
    }
    if (ty == 0) {
        float ssum = red[0][tx] + red[1][tx] + red[2][tx] + red[3][tx];
        atomicAdd(&g_S[b * 64 + tx], ssum);
    }
}

// One block per row i.
// Phase 1: atomic-free sorted neighbor compaction (adj row + forced diag).
// Phase 2 (tiled): coeffs (c, j*256) via factored exps into smem int2.
// Phase 3: warp b = batch b; 2 neighbors/iter; half-warp x float4 dims.
__global__ __launch_bounds__(256) void k_main(const float* __restrict__ adj,
                                              const float* __restrict__ bias,
                                              float* __restrict__ out) {
    __shared__ unsigned short nbr[N + 8];
    __shared__ int2 cj[8][TILE + 2];
    __shared__ float sh_negs[8], sh_f1[8], sh_fa[8];
    __shared__ int sh_wtot[8], sh_wbase[8], sh_cnt;
    int i = blockIdx.x, tid = threadIdx.x;
    int wid = tid >> 5, lane = tid & 31;

    if (tid < 8) {
        float4 se = g_se[tid * N + i];
        sh_negs[tid] = -se.x; sh_f1[tid] = se.y; sh_fa[tid] = se.z;
    }

    // ---- Phase 1: scan 8 contiguous adj entries per thread ----
    const float4* arow4 = (const float4*)(adj + (size_t)i * N);
    float4 v0 = arow4[tid * 2];
    float4 v1 = arow4[tid * 2 + 1];
    int j0 = tid * 8;
    unsigned bm = 0;
    bm |= (v0.x != 0.f) ? 1u : 0u;
    bm |= (v0.y != 0.f) ? 2u : 0u;
    bm |= (v0.z != 0.f) ? 4u : 0u;
    bm |= (v0.w != 0.f) ? 8u : 0u;
    bm |= (v1.x != 0.f) ? 16u : 0u;
    bm |= (v1.y != 0.f) ? 32u : 0u;
    bm |= (v1.z != 0.f) ? 64u : 0u;
    bm |= (v1.w != 0.f) ? 128u : 0u;
    if ((unsigned)(i - j0) < 8u) bm |= 1u << (i - j0);   // forced diagonal
    int lc = __popc(bm);
    // warp inclusive prefix of lc
    int pre = lc;
#pragma unroll
    for (int o = 1; o < 32; o <<= 1) {
        int u = __shfl_up_sync(0xffffffffu, pre, o);
        if (lane >= o) pre += u;
    }
    if (lane == 31) sh_wtot[wid] = pre;
    __syncthreads();
    if (tid == 0) {
        int run = 0;
#pragma unroll
        for (int w = 0; w < 8; w++) { sh_wbase[w] = run; run += sh_wtot[w]; }
        sh_cnt = run;
    }
    __syncthreads();
    int base = sh_wbase[wid] + pre - lc;
#pragma unroll
    for (int k = 0; k < 8; k++) {
        if (bm & (1u << k))
            nbr[base + __popc(bm & ((1u << k) - 1u))] = (unsigned short)(j0 + k);
    }
    __syncthreads();
    int cnt = sh_cnt;

    // ---- Phases 2+3, tiled ----
    int b = wid, hsel = lane >> 4, m = lane & 15;
    const char* hb = (const char*)g_h + (size_t)(b * N * D) * 4 + m * 16;
    float acc0 = 0.f, acc1 = 0.f, acc2 = 0.f, acc3 = 0.f, z = 0.f;

    for (int t0 = 0; t0 < cnt; t0 += TILE) {
        int tl = min(TILE, cnt - t0);
        // coefficients: idx -> (bb = idx>>8, kk = idx&255); pad slot at kk==tl
#pragma unroll
        for (int idx = tid; idx < 8 * TILE; idx += 256) {
            int bb = idx >> 8;
            int kk = idx & (TILE - 1);
            if (kk < tl) {
                int j = nbr[t0 + kk];
                float4 te = g_te[bb * N + j];
                float c = (te.x > sh_negs[bb]) ? fmaf(sh_f1[bb], te.y, -1.f)
                                               : fmaf(sh_fa[bb], te.z, -1.f);
                cj[bb][kk] = make_int2(__float_as_int(c), j << 8);
            } else if (kk == tl) {
                cj[bb][kk] = make_int2(0, 0);
            }
        }
        __syncthreads();
        int pairs = (tl + 1) >> 1;
#pragma unroll 2
        for (int p = 0; p < pairs; p++) {
            int2 e = cj[b][2 * p + hsel];
            float c = __int_as_float(e.x);
            float4 hv = *(const float4*)(hb + e.y);
            acc0 = fmaf(c, hv.x, acc0);
            acc1 = fmaf(c, hv.y, acc1);
            acc2 = fmaf(c, hv.z, acc2);
            acc3 = fmaf(c, hv.w, acc3);
            z += c;
        }
        __syncthreads();
    }
    // combine even/odd neighbor halves
    acc0 += __shfl_xor_sync(0xffffffffu, acc0, 16);
    acc1 += __shfl_xor_sync(0xffffffffu, acc1, 16);
    acc2 += __shfl_xor_sync(0xffffffffu, acc2, 16);
    acc3 += __shfl_xor_sync(0xffffffffu, acc3, 16);
    z    += __shfl_xor_sync(0xffffffffu, z, 16);
    if (hsel == 0) {
        float inv = 1.f / ((float)N + z);
        float4 S4 = ((const float4*)g_S)[b * 16 + m];
        float4 b4 = ((const float4*)bias)[m];
        float4 o4;
        o4.x = (S4.x + acc0) * inv + b4.x;
        o4.y = (S4.y + acc1) * inv + b4.y;
        o4.z = (S4.z + acc2) * inv + b4.z;
        o4.w = (S4.w + acc3) * inv + b4.w;
        ((float4*)out)[(b * N + i) * 16 + m] = o4;
    }
}

extern "C" void kernel_launch(void* const* d_in, const int* in_sizes, int n_in,
                              void* d_out, int out_size) {
    const float* x    = (const float*)d_in[0];  // [B,N,64]
    const float* adj  = (const float*)d_in[1];  // [N,N]
    const float* W    = (const float*)d_in[2];  // [64,64]
    const float* a    = (const float*)d_in[3];  // [128,1]
    const float* bias = (const float*)d_in[4];  // [64]
    float* out = (float*)d_out;                 // [B,N,64]

    k_init<<<1, 512>>>();
    k_h<<<(B * N) / 32, dim3(64, 4)>>>(x, W, a);
    k_main<<<N, 256>>>(adj, bias, out);
}

// round 9
// speedup vs baseline: 2.3669x; 1.1289x over previous
#include <cuda_runtime.h>
#include <cuda_fp16.h>

#define B 8
#define N 2048
#define D 64
#define ALPHA 0.2f
#define TILE 256

// Scratch: h fp16 [B,N,D]; per-row exp packs; colsum accumulators + flags.
__device__ __align__(16) __half  g_hh[B * N * D];
__device__ __align__(16) float4  g_se[B * N];
__device__ __align__(16) float4  g_te[B * N];
__device__ __align__(16) float   g_S[B * D];    // finalized colsums
__device__ __align__(16) float   g_S2[B * D];   // atomic accumulators (zero-init, self-resetting)
__device__ int g_cnt[B];                        // zero-init, self-resetting

// Fused: h = x@W (fp16 out), colsums S (atomics + last-block finalize),
// s/t row-dots + exp packs. Block (64,4); 32 rows/block; grid = B*N/32 = 512.
__global__ __launch_bounds__(256) void k_h(const float* __restrict__ x,
                                           const float* __restrict__ W,
                                           const float* __restrict__ a) {
    __shared__ float Ws[64 * 64];
    __shared__ float xs[32 * 64];
    __shared__ float red[4][64];
    __shared__ float redS[8][4][2];
    __shared__ float redT[8][4][2];
    __shared__ int isLast;
    int tx = threadIdx.x, ty = threadIdx.y;
    int tid = ty * 64 + tx;

    const float4* W4 = (const float4*)W;
    float4* Ws4 = (float4*)Ws;
    for (int k = tid; k < 1024; k += 256) Ws4[k] = W4[k];
    int rowBase = blockIdx.x * 32;               // flattened over B*N (32 | N)
    int b = rowBase / N;
    const float4* x4 = ((const float4*)x) + rowBase * 16;
    float4* xs4 = (float4*)xs;
    for (int k = tid; k < 512; k += 256) xs4[k] = x4[k];
    __syncthreads();

    float a0 = a[tx];
    float a1 = a[64 + tx];
    float accs[8];
#pragma unroll
    for (int rt = 0; rt < 8; rt++) accs[rt] = 0.f;
    // Register-blocked GEMM: W values hoisted across the 8 rows.
#pragma unroll
    for (int i4 = 0; i4 < 16; i4++) {
        float w0 = Ws[(i4 * 4 + 0) * 64 + tx];
        float w1 = Ws[(i4 * 4 + 1) * 64 + tx];
        float w2 = Ws[(i4 * 4 + 2) * 64 + tx];
        float w3 = Ws[(i4 * 4 + 3) * 64 + tx];
#pragma unroll
        for (int rt = 0; rt < 8; rt++) {
            float4 xv = xs4[(rt * 4 + ty) * 16 + i4];   // broadcast within warp
            accs[rt] = fmaf(xv.x, w0, accs[rt]);
            accs[rt] = fmaf(xv.y, w1, accs[rt]);
            accs[rt] = fmaf(xv.z, w2, accs[rt]);
            accs[rt] = fmaf(xv.w, w3, accs[rt]);
        }
    }
    float part = 0.f;
#pragma unroll
    for (int rt = 0; rt < 8; rt++) {
        g_hh[(rowBase + rt * 4 + ty) * 64 + tx] = __float2half_rn(accs[rt]);
        part += accs[rt];
    }
    // s/t reductions: warp = (ty, 32-col half)
    int lane = tid & 31, half = tx >> 5;
#pragma unroll
    for (int rt = 0; rt < 8; rt++) {
        float sp = accs[rt] * a0;
        float tp = accs[rt] * a1;
#pragma unroll
        for (int o = 16; o > 0; o >>= 1) {
            sp += __shfl_xor_sync(0xffffffffu, sp, o);
            tp += __shfl_xor_sync(0xffffffffu, tp, o);
        }
        if (lane == 0) { redS[rt][ty][half] = sp; redT[rt][ty][half] = tp; }
    }
    red[ty][tx] = part;
    __syncthreads();
    if (tid < 32) {
        int rt = tid >> 2, tyy = tid & 3;
        float s = redS[rt][tyy][0] + redS[rt][tyy][1];
        float t = redT[rt][tyy][0] + redT[rt][tyy][1];
        int r = rowBase + rt * 4 + tyy;
        g_se[r] = make_float4(s, __expf(s), __expf(ALPHA * s), 0.f);
        g_te[r] = make_float4(t, __expf(t), __expf(ALPHA * t), 0.f);
    }
    if (ty == 0) {
        float ssum = red[0][tx] + red[1][tx] + red[2][tx] + red[3][tx];
        atomicAdd(&g_S2[b * 64 + tx], ssum);
    }
    __threadfence();
    if (tid == 0) {
        int old = atomicAdd(&g_cnt[b], 1);
        isLast = (old == 63);                      // 64 blocks per batch
    }
    __syncthreads();
    if (isLast && tid < 64) {                      // finalize + self-reset
        g_S[b * 64 + tid] = g_S2[b * 64 + tid];
        g_S2[b * 64 + tid] = 0.f;
        if (tid == 0) g_cnt[b] = 0;
    }
}

// One block per row i. Phase 1: atomic-free sorted neighbor compaction.
// Phase 2 (tiled): coeffs (c, j*128) via factored exps into smem int2.
// Phase 3: warp b = batch b; 2 neighbors/iter; fp16 h gather (128B/row).
__global__ __launch_bounds__(256) void k_main(const float* __restrict__ adj,
                                              const float* __restrict__ bias,
                                              float* __restrict__ out) {
    __shared__ unsigned short nbr[N + 8];
    __shared__ int2 cj[8][TILE + 2];
    __shared__ float sh_negs[8], sh_f1[8], sh_fa[8];
    __shared__ int sh_wtot[8], sh_wbase[8], sh_cnt;
    int i = blockIdx.x, tid = threadIdx.x;
    int wid = tid >> 5, lane = tid & 31;

    if (tid < 8) {
        float4 se = g_se[tid * N + i];
        sh_negs[tid] = -se.x; sh_f1[tid] = se.y; sh_fa[tid] = se.z;
    }

    // ---- Phase 1: scan 8 contiguous adj entries per thread ----
    const float4* arow4 = (const float4*)(adj + (size_t)i * N);
    float4 v0 = arow4[tid * 2];
    float4 v1 = arow4[tid * 2 + 1];
    int j0 = tid * 8;
    unsigned bm = 0;
    bm |= (v0.x != 0.f) ? 1u : 0u;
    bm |= (v0.y != 0.f) ? 2u : 0u;
    bm |= (v0.z != 0.f) ? 4u : 0u;
    bm |= (v0.w != 0.f) ? 8u : 0u;
    bm |= (v1.x != 0.f) ? 16u : 0u;
    bm |= (v1.y != 0.f) ? 32u : 0u;
    bm |= (v1.z != 0.f) ? 64u : 0u;
    bm |= (v1.w != 0.f) ? 128u : 0u;
    if ((unsigned)(i - j0) < 8u) bm |= 1u << (i - j0);   // forced diagonal
    int lc = __popc(bm);
    int pre = lc;
#pragma unroll
    for (int o = 1; o < 32; o <<= 1) {
        int u = __shfl_up_sync(0xffffffffu, pre, o);
        if (lane >= o) pre += u;
    }
    if (lane == 31) sh_wtot[wid] = pre;
    __syncthreads();
    if (tid == 0) {
        int run = 0;
#pragma unroll
        for (int w = 0; w < 8; w++) { sh_wbase[w] = run; run += sh_wtot[w]; }
        sh_cnt = run;
    }
    __syncthreads();
    int base = sh_wbase[wid] + pre - lc;
#pragma unroll
    for (int k = 0; k < 8; k++) {
        if (bm & (1u << k))
            nbr[base + __popc(bm & ((1u << k) - 1u))] = (unsigned short)(j0 + k);
    }
    __syncthreads();
    int cnt = sh_cnt;

    // ---- Phases 2+3, tiled ----
    int b = wid, hsel = lane >> 4, m = lane & 15;
    const char* hb = (const char*)g_hh + (size_t)(b * N * D) * 2 + m * 8;
    float acc0 = 0.f, acc1 = 0.f, acc2 = 0.f, acc3 = 0.f, z = 0.f;

    for (int t0 = 0; t0 < cnt; t0 += TILE) {
        int tl = min(TILE, cnt - t0);
#pragma unroll
        for (int idx = tid; idx < 8 * TILE; idx += 256) {
            int bb = idx >> 8;
            int kk = idx & (TILE - 1);
            if (kk < tl) {
                int j = nbr[t0 + kk];
                float4 te = g_te[bb * N + j];
                float c = (te.x > sh_negs[bb]) ? fmaf(sh_f1[bb], te.y, -1.f)
                                               : fmaf(sh_fa[bb], te.z, -1.f);
                cj[bb][kk] = make_int2(__float_as_int(c), j << 7);  // 128B rows
            } else if (kk == tl) {
                cj[bb][kk] = make_int2(0, 0);
            }
        }
        __syncthreads();
        int pairs = (tl + 1) >> 1;
#pragma unroll 4
        for (int p = 0; p < pairs; p++) {
            int2 e = cj[b][2 * p + hsel];
            float c = __int_as_float(e.x);
            uint2 hv = *(const uint2*)(hb + e.y);    // 4 halves, 1 L2 line/row
            float2 f0 = __half22float2(*(const __half2*)&hv.x);
            float2 f1 = __half22float2(*(const __half2*)&hv.y);
            acc0 = fmaf(c, f0.x, acc0);
            acc1 = fmaf(c, f0.y, acc1);
            acc2 = fmaf(c, f1.x, acc2);
            acc3 = fmaf(c, f1.y, acc3);
            z += c;
        }
        __syncthreads();
    }
    // combine even/odd neighbor halves
    acc0 += __shfl_xor_sync(0xffffffffu, acc0, 16);
    acc1 += __shfl_xor_sync(0xffffffffu, acc1, 16);
    acc2 += __shfl_xor_sync(0xffffffffu, acc2, 16);
    acc3 += __shfl_xor_sync(0xffffffffu, acc3, 16);
    z    += __shfl_xor_sync(0xffffffffu, z, 16);
    if (hsel == 0) {
        float inv = 1.f / ((float)N + z);
        float4 S4 = ((const float4*)g_S)[b * 16 + m];
        float4 b4 = ((const float4*)bias)[m];
        float4 o4;
        o4.x = (S4.x + acc0) * inv + b4.x;
        o4.y = (S4.y + acc1) * inv + b4.y;
        o4.z = (S4.z + acc2) * inv + b4.z;
        o4.w = (S4.w + acc3) * inv + b4.w;
        ((float4*)out)[(b * N + i) * 16 + m] = o4;
    }
}

extern "C" void kernel_launch(void* const* d_in, const int* in_sizes, int n_in,
                              void* d_out, int out_size) {
    const float* x    = (const float*)d_in[0];  // [B,N,64]
    const float* adj  = (const float*)d_in[1];  // [N,N]
    const float* W    = (const float*)d_in[2];  // [64,64]
    const float* a    = (const float*)d_in[3];  // [128,1]
    const float* bias = (const float*)d_in[4];  // [64]
    float* out = (float*)d_out;                 // [B,N,64]

    k_h<<<(B * N) / 32, dim3(64, 4)>>>(x, W, a);
    k_main<<<N, 256>>>(adj, bias, out);
}

// round 12
// speedup vs baseline: 2.8326x; 1.1968x over previous
#include <cuda_runtime.h>
#include <cuda_fp16.h>

#define B 8
#define N 2048
#define D 64
#define ALPHA 0.2f

// Scratch: h fp16 [B,N,D]; per-row exp packs; colsum accumulators + flags.
__device__ __align__(16) __half  g_hh[B * N * D];
__device__ __align__(16) float4  g_se[B * N];
__device__ __align__(16) float4  g_te[B * N];
__device__ __align__(16) float   g_S[B * D];    // finalized colsums
__device__ __align__(16) float   g_S2[B * D];   // atomic accumulators (zero-init, self-resetting)
__device__ int g_cnt[B];                        // zero-init, self-resetting

// Fused: h = x@W (fp16 out), colsums S (atomics + last-block finalize),
// s/t row-dots + exp packs. Block (64,4); 32 rows/block; grid = B*N/32 = 512.
__global__ __launch_bounds__(256) void k_h(const float* __restrict__ x,
                                           const float* __restrict__ W,
                                           const float* __restrict__ a) {
    __shared__ float Ws[64 * 64];
    __shared__ float xs[32 * 64];
    __shared__ float red[4][64];
    __shared__ float redS[8][4][2];
    __shared__ float redT[8][4][2];
    __shared__ int isLast;
    int tx = threadIdx.x, ty = threadIdx.y;
    int tid = ty * 64 + tx;

    const float4* W4 = (const float4*)W;
    float4* Ws4 = (float4*)Ws;
    for (int k = tid; k < 1024; k += 256) Ws4[k] = W4[k];
    int rowBase = blockIdx.x * 32;               // flattened over B*N (32 | N)
    int b = rowBase / N;
    const float4* x4 = ((const float4*)x) + rowBase * 16;
    float4* xs4 = (float4*)xs;
    for (int k = tid; k < 512; k += 256) xs4[k] = x4[k];
    __syncthreads();

    float a0 = a[tx];
    float a1 = a[64 + tx];
    float accs[8];
#pragma unroll
    for (int rt = 0; rt < 8; rt++) accs[rt] = 0.f;
#pragma unroll
    for (int i4 = 0; i4 < 16; i4++) {
        float w0 = Ws[(i4 * 4 + 0) * 64 + tx];
        float w1 = Ws[(i4 * 4 + 1) * 64 + tx];
        float w2 = Ws[(i4 * 4 + 2) * 64 + tx];
        float w3 = Ws[(i4 * 4 + 3) * 64 + tx];
#pragma unroll
        for (int rt = 0; rt < 8; rt++) {
            float4 xv = xs4[(rt * 4 + ty) * 16 + i4];
            accs[rt] = fmaf(xv.x, w0, accs[rt]);
            accs[rt] = fmaf(xv.y, w1, accs[rt]);
            accs[rt] = fmaf(xv.z, w2, accs[rt]);
            accs[rt] = fmaf(xv.w, w3, accs[rt]);
        }
    }
    float part = 0.f;
#pragma unroll
    for (int rt = 0; rt < 8; rt++) {
        g_hh[(rowBase + rt * 4 + ty) * 64 + tx] = __float2half_rn(accs[rt]);
        part += accs[rt];
    }
    int lane = tid & 31, half = tx >> 5;
#pragma unroll
    for (int rt = 0; rt < 8; rt++) {
        float sp = accs[rt] * a0;
        float tp = accs[rt] * a1;
#pragma unroll
        for (int o = 16; o > 0; o >>= 1) {
            sp += __shfl_xor_sync(0xffffffffu, sp, o);
            tp += __shfl_xor_sync(0xffffffffu, tp, o);
        }
        if (lane == 0) { redS[rt][ty][half] = sp; redT[rt][ty][half] = tp; }
    }
    red[ty][tx] = part;
    __syncthreads();
    if (tid < 32) {
        int rt = tid >> 2, tyy = tid & 3;
        float s = redS[rt][tyy][0] + redS[rt][tyy][1];
        float t = redT[rt][tyy][0] + redT[rt][tyy][1];
        int r = rowBase + rt * 4 + tyy;
        g_se[r] = make_float4(s, __expf(s), __expf(ALPHA * s), 0.f);
        g_te[r] = make_float4(t, __expf(t), __expf(ALPHA * t), 0.f);
    }
    if (ty == 0) {
        float ssum = red[0][tx] + red[1][tx] + red[2][tx] + red[3][tx];
        atomicAdd(&g_S2[b * 64 + tx], ssum);
    }
    __threadfence();
    if (tid == 0) {
        int old = atomicAdd(&g_cnt[b], 1);
        isLast = (old == 63);
    }
    __syncthreads();
    if (isLast && tid < 64) {
        g_S[b * 64 + tid] = g_S2[b * 64 + tid];
        g_S2[b * 64 + tid] = 0.f;
        if (tid == 0) g_cnt[b] = 0;
    }
}

// One block per row i. Phase 1: atomic-free sorted neighbor compaction.
// Phase 2: warp b = batch b; 4 neighbors/warp-iter (quarter-warp each, in-lane
// factored-exp coefficients, no smem staging, no barriers).
__global__ __launch_bounds__(256) void k_main(const float* __restrict__ adj,
                                              const float* __restrict__ bias,
                                              float* __restrict__ out) {
    __shared__ unsigned short nbr[N + 8];
    __shared__ float sh_negs[8], sh_f1[8], sh_fa[8];
    __shared__ int sh_wtot[8], sh_wbase[8], sh_cnt;
    int i = blockIdx.x, tid = threadIdx.x;
    int wid = tid >> 5, lane = tid & 31;

    if (tid < 8) {
        float4 se = g_se[tid * N + i];
        sh_negs[tid] = -se.x; sh_f1[tid] = se.y; sh_fa[tid] = se.z;
    }

    // ---- Phase 1: scan 8 contiguous adj entries per thread ----
    const float4* arow4 = (const float4*)(adj + (size_t)i * N);
    float4 v0 = arow4[tid * 2];
    float4 v1 = arow4[tid * 2 + 1];
    int j0 = tid * 8;
    unsigned bm = 0;
    bm |= (v0.x != 0.f) ? 1u : 0u;
    bm |= (v0.y != 0.f) ? 2u : 0u;
    bm |= (v0.z != 0.f) ? 4u : 0u;
    bm |= (v0.w != 0.f) ? 8u : 0u;
    bm |= (v1.x != 0.f) ? 16u : 0u;
    bm |= (v1.y != 0.f) ? 32u : 0u;
    bm |= (v1.z != 0.f) ? 64u : 0u;
    bm |= (v1.w != 0.f) ? 128u : 0u;
    if ((unsigned)(i - j0) < 8u) bm |= 1u << (i - j0);   // forced diagonal
    int lc = __popc(bm);
    int pre = lc;
#pragma unroll
    for (int o = 1; o < 32; o <<= 1) {
        int u = __shfl_up_sync(0xffffffffu, pre, o);
        if (lane >= o) pre += u;
    }
    if (lane == 31) sh_wtot[wid] = pre;
    __syncthreads();
    if (tid == 0) {
        int run = 0;
#pragma unroll
        for (int w = 0; w < 8; w++) { sh_wbase[w] = run; run += sh_wtot[w]; }
        sh_cnt = run;
    }
    __syncthreads();
    int base = sh_wbase[wid] + pre - lc;
#pragma unroll
    for (int k = 0; k < 8; k++) {
        if (bm & (1u << k))
            nbr[base + __popc(bm & ((1u << k) - 1u))] = (unsigned short)(j0 + k);
    }
    __syncthreads();
    int cnt = sh_cnt;

    // ---- Phase 2: gather-accumulate, 4 neighbors per warp-iteration ----
    int b = wid, sub = lane >> 3, d8 = lane & 7;
    float negs = sh_negs[b], f1 = sh_f1[b], fa = sh_fa[b];
    const float4* teb = (const float4*)&g_te[b * N];
    const char* hb = (const char*)g_hh + (size_t)(b * N * D) * 2 + d8 * 16;
    float a0 = 0.f, a1 = 0.f, a2 = 0.f, a3 = 0.f;
    float a4 = 0.f, a5 = 0.f, a6 = 0.f, a7 = 0.f, z = 0.f;
    int quads = (cnt + 3) >> 2;
#pragma unroll 4
    for (int q = 0; q < quads; q++) {
        int k = q * 4 + sub;
        bool valid = k < cnt;
        int j = valid ? (int)nbr[k] : 0;
        float4 te = teb[j];
        float c = (te.x > negs) ? fmaf(f1, te.y, -1.f)
                                : fmaf(fa, te.z, -1.f);
        c = valid ? c : 0.f;
        uint4 hv = *(const uint4*)(hb + (j << 7));   // 16B of the 128B row
        float2 p0 = __half22float2(*(const __half2*)&hv.x);
        float2 p1 = __half22float2(*(const __half2*)&hv.y);
        float2 p2 = __half22float2(*(const __half2*)&hv.z);
        float2 p3 = __half22float2(*(const __half2*)&hv.w);
        a0 = fmaf(c, p0.x, a0); a1 = fmaf(c, p0.y, a1);
        a2 = fmaf(c, p1.x, a2); a3 = fmaf(c, p1.y, a3);
        a4 = fmaf(c, p2.x, a4); a5 = fmaf(c, p2.y, a5);
        a6 = fmaf(c, p3.x, a6); a7 = fmaf(c, p3.y, a7);
        z += c;
    }
    // reduce across the 4 sub-groups (lane bits 3,4)
#pragma unroll
    for (int o = 8; o <= 16; o <<= 1) {
        a0 += __shfl_xor_sync(0xffffffffu, a0, o);
        a1 += __shfl_xor_sync(0xffffffffu, a1, o);
        a2 += __shfl_xor_sync(0xffffffffu, a2, o);
        a3 += __shfl_xor_sync(0xffffffffu, a3, o);
        a4 += __shfl_xor_sync(0xffffffffu, a4, o);
        a5 += __shfl_xor_sync(0xffffffffu, a5, o);
        a6 += __shfl_xor_sync(0xffffffffu, a6, o);
        a7 += __shfl_xor_sync(0xffffffffu, a7, o);
        z  += __shfl_xor_sync(0xffffffffu, z, o);
    }
    if (sub == 0) {                       // lanes 0-7: dims d8*8 .. d8*8+7
        float inv = 1.f / ((float)N + z);
        const float4* S4 = (const float4*)&g_S[b * 64 + d8 * 8];
        const float4* b4 = (const float4*)&bias[d8 * 8];
        float4 S0 = S4[0], S1 = S4[1], bb0 = b4[0], bb1 = b4[1];
        float4 o0, o1;
        o0.x = (S0.x + a0) * inv + bb0.x;
        o0.y = (S0.y + a1) * inv + bb0.y;
        o0.z = (S0.z + a2) * inv + bb0.z;
        o0.w = (S0.w + a3) * inv + bb0.w;
        o1.x = (S1.x + a4) * inv + bb1.x;
        o1.y = (S1.y + a5) * inv + bb1.y;
        o1.z = (S1.z + a6) * inv + bb1.z;
        o1.w = (S1.w + a7) * inv + bb1.w;
        float4* op = (float4*)(out + (size_t)(b * N + i) * 64 + d8 * 8);
        op[0] = o0;
        op[1] = o1;
    }
}

extern "C" void kernel_launch(void* const* d_in, const int* in_sizes, int n_in,
                              void* d_out, int out_size) {
    const float* x    = (const float*)d_in[0];  // [B,N,64]
    const float* adj  = (const float*)d_in[1];  // [N,N]
    const float* W    = (const float*)d_in[2];  // [64,64]
    const float* a    = (const float*)d_in[3];  // [128,1]
    const float* bias = (const float*)d_in[4];  // [64]
    float* out = (float*)d_out;                 // [B,N,64]

    k_h<<<(B * N) / 32, dim3(64, 4)>>>(x, W, a);
    k_main<<<N, 256>>>(adj, bias, out);
}

// round 13
// speedup vs baseline: 3.0164x; 1.0649x over previous
#include <cuda_runtime.h>
#include <cuda_fp16.h>

#define B 8
#define N 2048
#define D 64
#define ALPHA 0.2f

// Scratch: h fp16 [B,N,D]; per-row exp packs (e^s,e^{as}) / (e^t,e^{at});
// colsum accumulators + flags.
__device__ __align__(16) __half  g_hh[B * N * D];
__device__ __align__(16) float2  g_se[B * N];
__device__ __align__(16) float2  g_te[B * N];
__device__ __align__(16) float   g_S[B * D];    // finalized colsums
__device__ __align__(16) float   g_S2[B * D];   // atomic accumulators (zero-init, self-resetting)
__device__ int g_cnt[B];                        // zero-init, self-resetting

// Fused: h = x@W (fp16 out), colsums S (atomics + last-block finalize),
// s/t row-dots + exp packs. Block (64,4); 32 rows/block; grid = B*N/32 = 512.
__global__ __launch_bounds__(256) void k_h(const float* __restrict__ x,
                                           const float* __restrict__ W,
                                           const float* __restrict__ a) {
    __shared__ float Ws[64 * 64];
    __shared__ float xs[32 * 64];
    __shared__ float red[4][64];
    __shared__ float redS[8][4][2];
    __shared__ float redT[8][4][2];
    __shared__ int isLast;
    int tx = threadIdx.x, ty = threadIdx.y;
    int tid = ty * 64 + tx;

    const float4* W4 = (const float4*)W;
    float4* Ws4 = (float4*)Ws;
    for (int k = tid; k < 1024; k += 256) Ws4[k] = W4[k];
    int rowBase = blockIdx.x * 32;               // flattened over B*N (32 | N)
    int b = rowBase / N;
    const float4* x4 = ((const float4*)x) + rowBase * 16;
    float4* xs4 = (float4*)xs;
    for (int k = tid; k < 512; k += 256) xs4[k] = x4[k];
    __syncthreads();

    float a0 = a[tx];
    float a1 = a[64 + tx];
    float accs[8];
#pragma unroll
    for (int rt = 0; rt < 8; rt++) accs[rt] = 0.f;
#pragma unroll
    for (int i4 = 0; i4 < 16; i4++) {
        float w0 = Ws[(i4 * 4 + 0) * 64 + tx];
        float w1 = Ws[(i4 * 4 + 1) * 64 + tx];
        float w2 = Ws[(i4 * 4 + 2) * 64 + tx];
        float w3 = Ws[(i4 * 4 + 3) * 64 + tx];
#pragma unroll
        for (int rt = 0; rt < 8; rt++) {
            float4 xv = xs4[(rt * 4 + ty) * 16 + i4];
            accs[rt] = fmaf(xv.x, w0, accs[rt]);
            accs[rt] = fmaf(xv.y, w1, accs[rt]);
            accs[rt] = fmaf(xv.z, w2, accs[rt]);
            accs[rt] = fmaf(xv.w, w3, accs[rt]);
        }
    }
    float part = 0.f;
#pragma unroll
    for (int rt = 0; rt < 8; rt++) {
        g_hh[(rowBase + rt * 4 + ty) * 64 + tx] = __float2half_rn(accs[rt]);
        part += accs[rt];
    }
    int lane = tid & 31, half = tx >> 5;
#pragma unroll
    for (int rt = 0; rt < 8; rt++) {
        float sp = accs[rt] * a0;
        float tp = accs[rt] * a1;
#pragma unroll
        for (int o = 16; o > 0; o >>= 1) {
            sp += __shfl_xor_sync(0xffffffffu, sp, o);
            tp += __shfl_xor_sync(0xffffffffu, tp, o);
        }
        if (lane == 0) { redS[rt][ty][half] = sp; redT[rt][ty][half] = tp; }
    }
    red[ty][tx] = part;
    __syncthreads();
    if (tid < 32) {
        int rt = tid >> 2, tyy = tid & 3;
        float s = redS[rt][tyy][0] + redS[rt][tyy][1];
        float t = redT[rt][tyy][0] + redT[rt][tyy][1];
        int r = rowBase + rt * 4 + tyy;
        g_se[r] = make_float2(__expf(s), __expf(ALPHA * s));
        g_te[r] = make_float2(__expf(t), __expf(ALPHA * t));
    }
    if (ty == 0) {
        float ssum = red[0][tx] + red[1][tx] + red[2][tx] + red[3][tx];
        atomicAdd(&g_S2[b * 64 + tx], ssum);
    }
    __threadfence();             // order this thread's g_S2 atomic
    __syncthreads();             // ...and everyone's, before the signal
    if (tid == 0) {
        int old = atomicAdd(&g_cnt[b], 1);
        isLast = (old == 63);
        if (isLast) __threadfence();   // acquire before reading g_S2
    }
    __syncthreads();
    if (isLast && tid < 64) {
        g_S[b * 64 + tid] = g_S2[b * 64 + tid];
        g_S2[b * 64 + tid] = 0.f;
        if (tid == 0) g_cnt[b] = 0;
    }
}

// One block per row i. Phase 1: atomic-free sorted neighbor compaction.
// Phase 2: warp b = batch b; 4 neighbors/warp-iter (quarter-warp each).
// Coefficient via max-trick: c = max(e^s e^t, e^{as} e^{at}) - 1  (no branch,
// no s compare). Main loop branch-free; single predicated tail iteration.
__global__ __launch_bounds__(256) void k_main(const float* __restrict__ adj,
                                              const float* __restrict__ bias,
                                              float* __restrict__ out) {
    __shared__ unsigned short nbr[N + 8];
    __shared__ float sh_f1[8], sh_fa[8];
    __shared__ int sh_wtot[8], sh_wbase[8], sh_cnt;
    int i = blockIdx.x, tid = threadIdx.x;
    int wid = tid >> 5, lane = tid & 31;

    if (tid < 8) {
        float2 se = g_se[tid * N + i];
        sh_f1[tid] = se.x; sh_fa[tid] = se.y;
    }

    // ---- Phase 1: scan 8 contiguous adj entries per thread ----
    const float4* arow4 = (const float4*)(adj + (size_t)i * N);
    float4 v0 = arow4[tid * 2];
    float4 v1 = arow4[tid * 2 + 1];
    int j0 = tid * 8;
    unsigned bm = 0;
    bm |= (v0.x != 0.f) ? 1u : 0u;
    bm |= (v0.y != 0.f) ? 2u : 0u;
    bm |= (v0.z != 0.f) ? 4u : 0u;
    bm |= (v0.w != 0.f) ? 8u : 0u;
    bm |= (v1.x != 0.f) ? 16u : 0u;
    bm |= (v1.y != 0.f) ? 32u : 0u;
    bm |= (v1.z != 0.f) ? 64u : 0u;
    bm |= (v1.w != 0.f) ? 128u : 0u;
    if ((unsigned)(i - j0) < 8u) bm |= 1u << (i - j0);   // forced diagonal
    int lc = __popc(bm);
    int pre = lc;
#pragma unroll
    for (int o = 1; o < 32; o <<= 1) {
        int u = __shfl_up_sync(0xffffffffu, pre, o);
        if (lane >= o) pre += u;
    }
    if (lane == 31) sh_wtot[wid] = pre;
    __syncthreads();
    if (tid == 0) {
        int run = 0;
#pragma unroll
        for (int w = 0; w < 8; w++) { sh_wbase[w] = run; run += sh_wtot[w]; }
        sh_cnt = run;
    }
    __syncthreads();
    int base = sh_wbase[wid] + pre - lc;
#pragma unroll
    for (int k = 0; k < 8; k++) {
        if (bm & (1u << k))
            nbr[base + __popc(bm & ((1u << k) - 1u))] = (unsigned short)(j0 + k);
    }
    __syncthreads();
    int cnt = sh_cnt;

    // ---- Phase 2: gather-accumulate, 4 neighbors per warp-iteration ----
    int b = wid, sub = lane >> 3, d8 = lane & 7;
    float f1 = sh_f1[b], fa = sh_fa[b];
    const float2* teb = (const float2*)g_te + b * N;
    const char* hb = (const char*)g_hh + (size_t)(b * N * D) * 2 + d8 * 16;
    float a0 = 0.f, a1 = 0.f, a2 = 0.f, a3 = 0.f;
    float a4 = 0.f, a5 = 0.f, a6 = 0.f, a7 = 0.f, z = 0.f;
    int full = cnt & ~3;
#pragma unroll 4
    for (int k0 = 0; k0 < full; k0 += 4) {
        int j = (int)nbr[k0 + sub];
        float2 te = teb[j];
        float c = fmaxf(f1 * te.x, fa * te.y) - 1.f;
        uint4 hv = *(const uint4*)(hb + (j << 7));   // 16B of the 128B row
        float2 p0 = __half22float2(*(const __half2*)&hv.x);
        float2 p1 = __half22float2(*(const __half2*)&hv.y);
        float2 p2 = __half22float2(*(const __half2*)&hv.z);
        float2 p3 = __half22float2(*(const __half2*)&hv.w);
        a0 = fmaf(c, p0.x, a0); a1 = fmaf(c, p0.y, a1);
        a2 = fmaf(c, p1.x, a2); a3 = fmaf(c, p1.y, a3);
        a4 = fmaf(c, p2.x, a4); a5 = fmaf(c, p2.y, a5);
        a6 = fmaf(c, p3.x, a6); a7 = fmaf(c, p3.y, a7);
        z += c;
    }
    if (full < cnt) {            // tail: 1-3 neighbors, predicated
        int k = full + sub;
        bool valid = k < cnt;
        int j = valid ? (int)nbr[k] : 0;
        float2 te = teb[j];
        float c = fmaxf(f1 * te.x, fa * te.y) - 1.f;
        c = valid ? c : 0.f;
        uint4 hv = *(const uint4*)(hb + (j << 7));
        float2 p0 = __half22float2(*(const __half2*)&hv.x);
        float2 p1 = __half22float2(*(const __half2*)&hv.y);
        float2 p2 = __half22float2(*(const __half2*)&hv.z);
        float2 p3 = __half22float2(*(const __half2*)&hv.w);
        a0 = fmaf(c, p0.x, a0); a1 = fmaf(c, p0.y, a1);
        a2 = fmaf(c, p1.x, a2); a3 = fmaf(c, p1.y, a3);
        a4 = fmaf(c, p2.x, a4); a5 = fmaf(c, p2.y, a5);
        a6 = fmaf(c, p3.x, a6); a7 = fmaf(c, p3.y, a7);
        z += c;
    }
    // reduce across the 4 sub-groups (lane bits 3,4)
#pragma unroll
    for (int o = 8; o <= 16; o <<= 1) {
        a0 += __shfl_xor_sync(0xffffffffu, a0, o);
        a1 += __shfl_xor_sync(0xffffffffu, a1, o);
        a2 += __shfl_xor_sync(0xffffffffu, a2, o);
        a3 += __shfl_xor_sync(0xffffffffu, a3, o);
        a4 += __shfl_xor_sync(0xffffffffu, a4, o);
        a5 += __shfl_xor_sync(0xffffffffu, a5, o);
        a6 += __shfl_xor_sync(0xffffffffu, a6, o);
        a7 += __shfl_xor_sync(0xffffffffu, a7, o);
        z  += __shfl_xor_sync(0xffffffffu, z, o);
    }
    if (sub == 0) {                       // lanes 0-7: dims d8*8 .. d8*8+7
        float inv = 1.f / ((float)N + z);
        const float4* S4 = (const float4*)&g_S[b * 64 + d8 * 8];
        const float4* b4 = (const float4*)&bias[d8 * 8];
        float4 S0 = S4[0], S1 = S4[1], bb0 = b4[0], bb1 = b4[1];
        float4 o0, o1;
        o0.x = (S0.x + a0) * inv + bb0.x;
        o0.y = (S0.y + a1) * inv + bb0.y;
        o0.z = (S0.z + a2) * inv + bb0.z;
        o0.w = (S0.w + a3) * inv + bb0.w;
        o1.x = (S1.x + a4) * inv + bb1.x;
        o1.y = (S1.y + a5) * inv + bb1.y;
        o1.z = (S1.z + a6) * inv + bb1.z;
        o1.w = (S1.w + a7) * inv + bb1.w;
        float4* op = (float4*)(out + (size_t)(b * N + i) * 64 + d8 * 8);
        op[0] = o0;
        op[1] = o1;
    }
}

extern "C" void kernel_launch(void* const* d_in, const int* in_sizes, int n_in,
                              void* d_out, int out_size) {
    const float* x    = (const float*)d_in[0];  // [B,N,64]
    const float* adj  = (const float*)d_in[1];  // [N,N]
    const float* W    = (const float*)d_in[2];  // [64,64]
    const float* a    = (const float*)d_in[3];  // [128,1]
    const float* bias = (const float*)d_in[4];  // [64]
    float* out = (float*)d_out;                 // [B,N,64]

    k_h<<<(B * N) / 32, dim3(64, 4)>>>(x, W, a);
    k_main<<<N, 256>>>(adj, bias, out);
}